// round 5
// baseline (speedup 1.0000x reference)
#include <cuda_runtime.h>

// logLikelihood_loss: sum over (B,T,P) of -log(clip(bivariate_gaussian_pdf, 1e-10)) / P
// B=64, T=128, P=512 -> 4,194,304 elements. y_target: (...,3) f32, o_pred: (...,5) f32.
// HBM-bound streaming reduction. Log-domain formulation avoids exp/log round-trip.
//
// R4: (a) stage each block's contiguous region through shared memory so all
//     global loads are perfectly coalesced LDG.128 (the direct AoS loads had
//     80B/48B lane strides -> ~20/12 L1tex wavefronts per LDG, co-limiting the
//     kernel at DRAM=74%). The per-thread smem reads (20-float / 12-float AoS
//     records) are bank-conflict-free without padding: LDS.128 runs in 8-lane
//     phases and 20L mod 32 / 12L mod 32 are distinct over L=0..7.
//     (b) single-kernel last-block reduction (atomicInc with wrap, replay-safe)
//     replaces the zero_out kernel + global atomics -> one launch, no pre-zero.

#define N_ELEM   4194304
#define GROUPS   (N_ELEM / 4)        // 4 elements per thread
#define THREADS  256
#define BLOCKS   (GROUPS / THREADS)  // 4096

#define O4_PER_BLOCK (THREADS * 5)   // 1280 float4 = 20KB
#define Y4_PER_BLOCK (THREADS * 3)   //  768 float4 = 12KB

__device__ float        g_partials[BLOCKS];
__device__ unsigned int g_count = 0;   // wraps back to 0 via atomicInc -> replay-safe

// Accurate tanh from fast exp (independent of -use_fast_math's tanh.approx,
// whose abs error would poison 1-rho^2).
__device__ __forceinline__ float fast_tanh(float x) {
    float ax = fabsf(x);
    float e  = __expf(2.0f * ax);
    float t  = 1.0f - __fdividef(2.0f, e + 1.0f);
    return copysignf(t, x);
}

__global__ __launch_bounds__(THREADS)
void nll_kernel(const float* __restrict__ y, const float* __restrict__ o,
                float* __restrict__ out) {
    __shared__ float4 s_o[O4_PER_BLOCK];   // 20 KB
    __shared__ float4 s_y[Y4_PER_BLOCK];   // 12 KB
    __shared__ float  wsum[THREADS / 32];
    __shared__ int    s_last;

    const int t = threadIdx.x;
    const int b = blockIdx.x;

    // ── Stage: perfectly coalesced LDG.128 ────────────────────────────────
    const float4* o4 = reinterpret_cast<const float4*>(o) + (size_t)b * O4_PER_BLOCK;
    const float4* y4 = reinterpret_cast<const float4*>(y) + (size_t)b * Y4_PER_BLOCK;
#pragma unroll
    for (int k = 0; k < 5; k++) s_o[t + k * THREADS] = o4[t + k * THREADS];
#pragma unroll
    for (int k = 0; k < 3; k++) s_y[t + k * THREADS] = y4[t + k * THREADS];
    __syncthreads();

    // ── Compute: per-thread AoS records from smem (conflict-free LDS.128) ─
    const float* so = reinterpret_cast<const float*>(s_o) + 20 * t;  // 80B-aligned... 80t: 16B-aligned
    const float* sy = reinterpret_cast<const float*>(s_y) + 12 * t;  // 48t bytes: 16B-aligned

    float of[20], yf[12];
#pragma unroll
    for (int k = 0; k < 5; k++)
        reinterpret_cast<float4*>(of)[k] = reinterpret_cast<const float4*>(so)[k];
#pragma unroll
    for (int k = 0; k < 3; k++)
        reinterpret_cast<float4*>(yf)[k] = reinterpret_cast<const float4*>(sy)[k];

    const float LOG_2PI  = 1.8378770664093453f;   // ln(2*pi)
    const float CLAMP_HI = 23.025850929940457f;   // -ln(1e-10)

    float acc = 0.0f;
#pragma unroll
    for (int j = 0; j < 4; j++) {
        float mux = of[5 * j + 0];
        float muy = of[5 * j + 1];
        float lsx = of[5 * j + 2];   // log(sx)
        float lsy = of[5 * j + 3];   // log(sy)
        float cra = of[5 * j + 4];   // pre-tanh corr

        float y1 = yf[3 * j + 1];
        float y2 = yf[3 * j + 2];

        float inv_sx = __expf(-lsx);
        float inv_sy = __expf(-lsy);
        float nx = (y1 - mux) * inv_sx;
        float ny = (y2 - muy) * inv_sy;

        float tt = fast_tanh(cra);
        float om = fmaf(-tt, tt, 1.0f);            // 1 - rho^2 > 0
        float z  = fmaf(nx, nx, fmaf(ny, ny, -2.0f * tt * nx * ny));

        // -log pdf = z/(2*om) + log(2pi) + log(sx) + log(sy) + 0.5*log(om)
        float nll = 0.5f * __fdividef(z, om)
                  + (LOG_2PI + lsx + lsy + 0.5f * __logf(om));
        acc += fminf(nll, CLAMP_HI);               // == -log(clip(pdf, 1e-10))
    }

    // ── Block reduction ───────────────────────────────────────────────────
#pragma unroll
    for (int off = 16; off; off >>= 1)
        acc += __shfl_down_sync(0xffffffffu, acc, off);

    const int lane = t & 31;
    const int wid  = t >> 5;
    if (lane == 0) wsum[wid] = acc;
    __syncthreads();

    if (wid == 0) {
        float v = (lane < THREADS / 32) ? wsum[lane] : 0.0f;
#pragma unroll
        for (int off = 4; off; off >>= 1)
            v += __shfl_down_sync(0xffffffffu, v, off);
        if (lane == 0) {
            g_partials[b] = v;
            __threadfence();
            unsigned old = atomicInc(&g_count, BLOCKS - 1);  // wraps to 0 -> replay-safe
            s_last = (old == BLOCKS - 1);
        }
    }
    __syncthreads();

    // ── Last block: final reduction over 4096 partials (L2-resident) ──────
    if (s_last) {
        __threadfence();
        float v = 0.0f;
#pragma unroll
        for (int k = 0; k < BLOCKS / THREADS; k++)
            v += __ldcg(&g_partials[t + k * THREADS]);   // bypass L1 (cross-SM data)

#pragma unroll
        for (int off = 16; off; off >>= 1)
            v += __shfl_down_sync(0xffffffffu, v, off);
        if (lane == 0) wsum[wid] = v;
        __syncthreads();
        if (wid == 0) {
            float s = (lane < THREADS / 32) ? wsum[lane] : 0.0f;
#pragma unroll
            for (int off = 4; off; off >>= 1)
                s += __shfl_down_sync(0xffffffffu, s, off);
            if (lane == 0)
                out[0] = s * (1.0f / 512.0f);   // divide by P once
        }
    }
}

extern "C" void kernel_launch(void* const* d_in, const int* in_sizes, int n_in,
                              void* d_out, int out_size) {
    const float* y = (const float*)d_in[0];   // y_target, 12,582,912 floats
    const float* o = (const float*)d_in[1];   // o_pred,  20,971,520 floats
    float* out = (float*)d_out;               // scalar fp32

    nll_kernel<<<BLOCKS, THREADS>>>(y, o, out);
}

// round 6
// speedup vs baseline: 1.0656x; 1.0656x over previous
#include <cuda_runtime.h>

// logLikelihood_loss: sum over (B,T,P) of -log(clip(bivariate_gaussian_pdf, 1e-10)) / P
// B=64, T=128, P=512 -> 4,194,304 elements. y_target: (...,3) f32, o_pred: (...,5) f32.
// HBM-bound streaming reduction. Log-domain formulation avoids exp/log round-trip.
//
// R5: revert R4's smem staging (occupancy + barrier costs outweighed the
//     nonexistent wavefront win: total L1tex wavefronts = bytes/128 regardless
//     of access pattern). Keep R1's direct float4 AoS loads (DRAM=74%) and the
//     single-launch last-block reduction (rel_err 0.0 in R4). New: grid-stride
//     loop with GRID = 148*8 = 1184 blocks (= exactly one full-occupancy wave)
//     to kill the 3.46-wave quantization tail (~9% of runtime) and raise MLP.

#define N_ELEM   4194304
#define GROUPS   (N_ELEM / 4)          // 1,048,576 groups of 4 records
#define THREADS  256
#define GRID     (148 * 8)             // 1184 blocks = one full wave at occ=8
#define STRIDE   (GRID * THREADS)      // 303,104 threads

__device__ float        g_partials[GRID];
__device__ unsigned int g_count = 0;   // atomicInc wraps to 0 -> graph-replay-safe

// Accurate tanh from fast exp (independent of -use_fast_math's tanh.approx,
// whose abs error would poison 1-rho^2).
__device__ __forceinline__ float fast_tanh(float x) {
    float ax = fabsf(x);
    float e  = __expf(2.0f * ax);
    float t  = 1.0f - __fdividef(2.0f, e + 1.0f);
    return copysignf(t, x);
}

__global__ __launch_bounds__(THREADS)
void nll_kernel(const float* __restrict__ y, const float* __restrict__ o,
                float* __restrict__ out) {
    const int t = threadIdx.x;
    const int b = blockIdx.x;

    const float LOG_2PI  = 1.8378770664093453f;   // ln(2*pi)
    const float CLAMP_HI = 23.025850929940457f;   // -ln(1e-10)

    float acc = 0.0f;

    // Grid-stride over groups of 4 consecutive records.
    for (int g = b * THREADS + t; g < GROUPS; g += STRIDE) {
        const float4* o4 = reinterpret_cast<const float4*>(o) + (size_t)g * 5;
        const float4* y4 = reinterpret_cast<const float4*>(y) + (size_t)g * 3;

        float of[20], yf[12];
#pragma unroll
        for (int k = 0; k < 5; k++) reinterpret_cast<float4*>(of)[k] = o4[k];
#pragma unroll
        for (int k = 0; k < 3; k++) reinterpret_cast<float4*>(yf)[k] = y4[k];

#pragma unroll
        for (int j = 0; j < 4; j++) {
            float mux = of[5 * j + 0];
            float muy = of[5 * j + 1];
            float lsx = of[5 * j + 2];   // log(sx)
            float lsy = of[5 * j + 3];   // log(sy)
            float cra = of[5 * j + 4];   // pre-tanh corr

            float y1 = yf[3 * j + 1];
            float y2 = yf[3 * j + 2];

            float inv_sx = __expf(-lsx);
            float inv_sy = __expf(-lsy);
            float nx = (y1 - mux) * inv_sx;
            float ny = (y2 - muy) * inv_sy;

            float tt = fast_tanh(cra);
            float om = fmaf(-tt, tt, 1.0f);            // 1 - rho^2 > 0
            float z  = fmaf(nx, nx, fmaf(ny, ny, -2.0f * tt * nx * ny));

            // -log pdf = z/(2*om) + log(2pi) + log(sx) + log(sy) + 0.5*log(om)
            float nll = 0.5f * __fdividef(z, om)
                      + (LOG_2PI + lsx + lsy + 0.5f * __logf(om));
            acc += fminf(nll, CLAMP_HI);               // == -log(clip(pdf, 1e-10))
        }
    }

    // ── Block reduction ───────────────────────────────────────────────────
#pragma unroll
    for (int off = 16; off; off >>= 1)
        acc += __shfl_down_sync(0xffffffffu, acc, off);

    __shared__ float wsum[THREADS / 32];
    __shared__ int   s_last;
    const int lane = t & 31;
    const int wid  = t >> 5;
    if (lane == 0) wsum[wid] = acc;
    __syncthreads();

    if (wid == 0) {
        float v = (lane < THREADS / 32) ? wsum[lane] : 0.0f;
#pragma unroll
        for (int off = 4; off; off >>= 1)
            v += __shfl_down_sync(0xffffffffu, v, off);
        if (lane == 0) {
            g_partials[b] = v;
            __threadfence();
            unsigned old = atomicInc(&g_count, GRID - 1);  // wraps -> replay-safe
            s_last = (old == GRID - 1);
        }
    }
    __syncthreads();

    // ── Last block: final reduction over 1184 partials (L2-resident) ──────
    if (s_last) {
        __threadfence();
        float v = 0.0f;
        for (int k = t; k < GRID; k += THREADS)
            v += __ldcg(&g_partials[k]);   // bypass L1 (cross-SM data)

#pragma unroll
        for (int off = 16; off; off >>= 1)
            v += __shfl_down_sync(0xffffffffu, v, off);
        if (lane == 0) wsum[wid] = v;
        __syncthreads();
        if (wid == 0) {
            float s = (lane < THREADS / 32) ? wsum[lane] : 0.0f;
#pragma unroll
            for (int off = 4; off; off >>= 1)
                s += __shfl_down_sync(0xffffffffu, s, off);
            if (lane == 0)
                out[0] = s * (1.0f / 512.0f);   // divide by P once
        }
    }
}

extern "C" void kernel_launch(void* const* d_in, const int* in_sizes, int n_in,
                              void* d_out, int out_size) {
    const float* y = (const float*)d_in[0];   // y_target, 12,582,912 floats
    const float* o = (const float*)d_in[1];   // o_pred,  20,971,520 floats
    float* out = (float*)d_out;               // scalar fp32

    nll_kernel<<<GRID, THREADS>>>(y, o, out);
}

// round 7
// speedup vs baseline: 1.1317x; 1.0620x over previous
#include <cuda_runtime.h>

// logLikelihood_loss: sum over (B,T,P) of -log(clip(bivariate_gaussian_pdf, 1e-10)) / P
// B=64, T=128, P=512 -> 4,194,304 elements. y_target: (...,3) f32, o_pred: (...,5) f32.
// HBM-bound streaming reduction. Log-domain formulation avoids exp/log round-trip.
//
// R6: R5's grid-stride failed because regs crept 32->34 (alloc 40) -> occ 6, so
//     GRID=1184 became 1.33 waves (occ=66.6%, DRAM=59%). Fix: __launch_bounds__
//     (256, 8) forces <=32 regs so occ=8 holds and GRID = 148*8 = 1184 is truly
//     one full wave. Inputs loaded with __ldcs (pure streaming, no reuse).

#define N_ELEM   4194304
#define GROUPS   (N_ELEM / 4)          // 1,048,576 groups of 4 records
#define THREADS  256
#define GRID     (148 * 8)             // 1184 blocks = one full wave at occ=8
#define STRIDE   (GRID * THREADS)      // 303,104 threads

__device__ float        g_partials[GRID];
__device__ unsigned int g_count = 0;   // atomicInc wraps to 0 -> graph-replay-safe

// Accurate tanh from fast exp (independent of -use_fast_math's tanh.approx,
// whose abs error would poison 1-rho^2).
__device__ __forceinline__ float fast_tanh(float x) {
    float ax = fabsf(x);
    float e  = __expf(2.0f * ax);
    float t  = 1.0f - __fdividef(2.0f, e + 1.0f);
    return copysignf(t, x);
}

__global__ __launch_bounds__(THREADS, 8)   // force <=32 regs -> occ=8 guaranteed
void nll_kernel(const float* __restrict__ y, const float* __restrict__ o,
                float* __restrict__ out) {
    const int t = threadIdx.x;
    const int b = blockIdx.x;

    const float LOG_2PI  = 1.8378770664093453f;   // ln(2*pi)
    const float CLAMP_HI = 23.025850929940457f;   // -ln(1e-10)

    float acc = 0.0f;

    // Grid-stride over groups of 4 consecutive records (3-4 iters/thread).
    for (int g = b * THREADS + t; g < GROUPS; g += STRIDE) {
        const float4* o4 = reinterpret_cast<const float4*>(o) + (size_t)g * 5;
        const float4* y4 = reinterpret_cast<const float4*>(y) + (size_t)g * 3;

        float of[20], yf[12];
#pragma unroll
        for (int k = 0; k < 5; k++) reinterpret_cast<float4*>(of)[k] = __ldcs(o4 + k);
#pragma unroll
        for (int k = 0; k < 3; k++) reinterpret_cast<float4*>(yf)[k] = __ldcs(y4 + k);

#pragma unroll
        for (int j = 0; j < 4; j++) {
            float mux = of[5 * j + 0];
            float muy = of[5 * j + 1];
            float lsx = of[5 * j + 2];   // log(sx)
            float lsy = of[5 * j + 3];   // log(sy)
            float cra = of[5 * j + 4];   // pre-tanh corr

            float y1 = yf[3 * j + 1];
            float y2 = yf[3 * j + 2];

            float inv_sx = __expf(-lsx);
            float inv_sy = __expf(-lsy);
            float nx = (y1 - mux) * inv_sx;
            float ny = (y2 - muy) * inv_sy;

            float tt = fast_tanh(cra);
            float om = fmaf(-tt, tt, 1.0f);            // 1 - rho^2 > 0
            float z  = fmaf(nx, nx, fmaf(ny, ny, -2.0f * tt * nx * ny));

            // -log pdf = z/(2*om) + log(2pi) + log(sx) + log(sy) + 0.5*log(om)
            float nll = 0.5f * __fdividef(z, om)
                      + (LOG_2PI + lsx + lsy + 0.5f * __logf(om));
            acc += fminf(nll, CLAMP_HI);               // == -log(clip(pdf, 1e-10))
        }
    }

    // ── Block reduction ───────────────────────────────────────────────────
#pragma unroll
    for (int off = 16; off; off >>= 1)
        acc += __shfl_down_sync(0xffffffffu, acc, off);

    __shared__ float wsum[THREADS / 32];
    __shared__ int   s_last;
    const int lane = t & 31;
    const int wid  = t >> 5;
    if (lane == 0) wsum[wid] = acc;
    __syncthreads();

    if (wid == 0) {
        float v = (lane < THREADS / 32) ? wsum[lane] : 0.0f;
#pragma unroll
        for (int off = 4; off; off >>= 1)
            v += __shfl_down_sync(0xffffffffu, v, off);
        if (lane == 0) {
            g_partials[b] = v;
            __threadfence();
            unsigned old = atomicInc(&g_count, GRID - 1);  // wraps -> replay-safe
            s_last = (old == GRID - 1);
        }
    }
    __syncthreads();

    // ── Last block: final reduction over 1184 partials (L2-resident) ──────
    if (s_last) {
        __threadfence();
        float v = 0.0f;
        for (int k = t; k < GRID; k += THREADS)
            v += __ldcg(&g_partials[k]);   // bypass L1 (cross-SM data)

#pragma unroll
        for (int off = 16; off; off >>= 1)
            v += __shfl_down_sync(0xffffffffu, v, off);
        if (lane == 0) wsum[wid] = v;
        __syncthreads();
        if (wid == 0) {
            float s = (lane < THREADS / 32) ? wsum[lane] : 0.0f;
#pragma unroll
            for (int off = 4; off; off >>= 1)
                s += __shfl_down_sync(0xffffffffu, s, off);
            if (lane == 0)
                out[0] = s * (1.0f / 512.0f);   // divide by P once
        }
    }
}

extern "C" void kernel_launch(void* const* d_in, const int* in_sizes, int n_in,
                              void* d_out, int out_size) {
    const float* y = (const float*)d_in[0];   // y_target, 12,582,912 floats
    const float* o = (const float*)d_in[1];   // o_pred,  20,971,520 floats
    float* out = (float*)d_out;               // scalar fp32

    nll_kernel<<<GRID, THREADS>>>(y, o, out);
}